// round 14
// baseline (speedup 1.0000x reference)
#include <cuda_runtime.h>
#include <math.h>

#define BATCH 256
#define NN    1024
#define PP    128
#define DIN   784
#define COUT  10
#define CH    64                     /* columns per k_run CTA */
#define RPC   16                     /* rows per k_run CTA */
#define NEV   64
#define NGRP  16                     /* row groups (blockIdx.y) */
#define GXS   16                     /* col chunks per group (blockIdx.x) */

#define TWO_PI_F 6.283185307179586f
#define DT       0.03125f
#define BETA_N   (2.0f/1024.0f)
#define A_ANC    0.08f
#define OME      (TWO_PI_F*200.0f)

typedef unsigned long long ull;

__device__ __forceinline__ ull pack2(float a, float b) {
    ull r; asm("mov.b64 %0,{%1,%2};" : "=l"(r) : "f"(a), "f"(b)); return r;
}
__device__ __forceinline__ ull fma2(ull a, ull b, ull c) {
    ull d; asm("fma.rn.f32x2 %0,%1,%2,%3;" : "=l"(d) : "l"(a), "l"(b), "l"(c));
    return d;
}
__device__ __forceinline__ float2 unpk(ull a) {
    float lo, hi;
    asm("mov.b64 {%0,%1},%2;" : "=f"(lo), "=f"(hi) : "l"(a));
    return make_float2(lo, hi);
}
__device__ __forceinline__ float hadd2(ull a) {
    float2 v = unpk(a); return v.x + v.y;
}
__device__ __forceinline__ unsigned su32(const void* p) {
    return (unsigned)__cvta_generic_to_shared(p);
}
#define CP16(dst, src) \
    asm volatile("cp.async.cg.shared.global [%0], [%1], 16;" :: "r"(dst), "l"(src))
#define CP_COMMIT() asm volatile("cp.async.commit_group;")
#define CP_WAIT(n)  asm volatile("cp.async.wait_group %0;" :: "n"(n))

/* m slot permutation: pattern p <-> storage slot.
   slot(p) = (p&64) + (p&15)*4 + ((p>>4)&3); inverse:
   p(s)    = (s&64) + ((s&63)>>2) + 16*(s&3). Each m_tail thread's 4
   partials land in 4 CONTIGUOUS slots -> one atomicAdd(float4). */
__device__ __forceinline__ int mslot(int p) {
    return (p & 64) + ((p & 15) << 2) + ((p >> 4) & 3);
}

struct EvalConsts { float sA[NEV]; float cA[NEV]; float cN[NEV]; };

/* ---- device scratch ---- */
__device__ float g_xc[PP*NN];
__device__ float g_xs[PP*NN];
__device__ float g_phi[BATCH*NN];
__device__ float g_fc[BATCH*NN];
__device__ float g_fs[BATCH*NN];
__device__ float g_m[3][BATCH*PP];   /* permuted slot layout */
__device__ unsigned g_cnt[NGRP*NEV];

/* ---- k_run shared layout (floats) ---- */
#define SW_STRIDE 130
#define SX_STRIDE 68
#define SC_STRIDE 68
#define OFF_XC   2080                 /* sW [16][130] = 2080 */
#define OFF_XS   (OFF_XC + 128*SX_STRIDE)        /* 10784 */
#define OFF_C    (OFF_XS + 128*SX_STRIDE)        /* 19488 */
#define OFF_S    (OFF_C + RPC*SC_STRIDE)         /* 20576 */
#define OFF_P    (OFF_S + RPC*SC_STRIDE)         /* 21664 */
#define OFF_A    (OFF_P + RPC*SC_STRIDE)         /* 22752 */
#define OFF_R    (OFF_A + RPC*SC_STRIDE)         /* 23840 */
#define SMEM_FLOATS (OFF_R + 256*8)              /* 25888 */
#define SMEM_BYTES  (SMEM_FLOATS*4)              /* 103552 -> 2 CTAs/SM */

/* encoder-private layout (proven 746 shapes, stride 36, 32 rows, CH 32) */
#define E_STRIDE 36
#define E_XC 4160
#define E_XS (E_XC + 128*E_STRIDE)
#define E_C  (E_XS + 128*E_STRIDE)
#define E_S  (E_C + 32*E_STRIDE)

/* ================= init ================================================= */
__global__ void k_init(const float* __restrict__ xi) {
    int i = blockIdx.x*256 + threadIdx.x;
    if (i < PP*NN) {
        float v = xi[i];
        g_xc[i] = cosf(v);
        g_xs[i] = sinf(v);
    }
    if (i < BATCH*PP) { g_m[0][i] = 0.f; g_m[1][i] = 0.f; }
    if (i < NGRP*NEV) g_cnt[i] = 0u;
}

/* ================= encoder (proven 746 version + mslot atomics) ========= */
__device__ __forceinline__ void m_tail_enc(const float* sC, const float* sS,
                                           const float* sXC, const float* sXS,
                                           float* mbuf, int r0) {
    int rb = threadIdx.x >> 5;
    int pb = threadIdx.x & 31;
    ull acc[16];
#pragma unroll
    for (int i = 0; i < 16; i++) acc[i] = 0ull;
    const float* cB  = sC  + (rb*4)*E_STRIDE;
    const float* sB  = sS  + (rb*4)*E_STRIDE;
    const float* xcB = sXC + pb*E_STRIDE;
    const float* xsB = sXS + pb*E_STRIDE;
#pragma unroll
    for (int nn = 0; nn < 32; nn += 4) {
        ulonglong2 cr[4], sr[4];
#pragma unroll
        for (int r = 0; r < 4; r++) {
            cr[r] = *(const ulonglong2*)&cB[r*E_STRIDE + nn];
            sr[r] = *(const ulonglong2*)&sB[r*E_STRIDE + nn];
        }
#pragma unroll
        for (int j = 0; j < 4; j++) {
            ulonglong2 xc2 = *(const ulonglong2*)&xcB[j*32*E_STRIDE + nn];
            ulonglong2 xs2 = *(const ulonglong2*)&xsB[j*32*E_STRIDE + nn];
#pragma unroll
            for (int r = 0; r < 4; r++) {
                ull a = acc[j*4 + r];
                a = fma2(cr[r].x, xc2.x, a);
                a = fma2(cr[r].y, xc2.y, a);
                a = fma2(sr[r].x, xs2.x, a);
                a = fma2(sr[r].y, xs2.y, a);
                acc[j*4 + r] = a;
            }
        }
    }
#pragma unroll
    for (int j = 0; j < 4; j++)
#pragma unroll
        for (int r = 0; r < 4; r++)
            atomicAdd(&mbuf[(r0 + rb*4 + r)*PP + mslot(pb + 32*j)],
                      hadd2(acc[j*4 + r]));
}

__global__ void __launch_bounds__(256, 2)
k_encoder(const float* __restrict__ x,
          const float* __restrict__ Wenc,
          const float* __restrict__ benc) {
    extern __shared__ float sm[];
    float* sA  = sm;
    float* sB  = sm + 32*17;
    float* sXC = sm + E_XC;
    float* sXS = sm + E_XS;
    float* sC  = sm + E_C;
    float* sS  = sm + E_S;

    int n0 = blockIdx.x*32, r0 = blockIdx.y*32;
    int tid = threadIdx.x;
    int row = tid >> 3, ng = tid & 7, nb = ng*4;

    float acc[4];
#pragma unroll
    for (int i = 0; i < 4; i++) acc[i] = 0.f;

    for (int d0 = 0; d0 < DIN; d0 += 16) {
        for (int i = tid; i < 512; i += 256) {
            int r = i >> 4, j = i & 15;
            sA[r*17 + j] = x[(r0+r)*DIN + d0 + j];
            sB[r*17 + j] = Wenc[(n0+r)*DIN + d0 + j];
        }
        __syncthreads();
#pragma unroll
        for (int j = 0; j < 16; j++) {
            float xa = sA[row*17 + j];
#pragma unroll
            for (int i = 0; i < 4; i++) acc[i] += xa * sB[(nb+i)*17 + j];
        }
        __syncthreads();
    }

    for (int i = tid; i < 128*8; i += 256) {
        int p = i >> 3, q = (i & 7) << 2;
        *(float4*)&sXC[p*E_STRIDE + q] = *(const float4*)&g_xc[p*NN + n0 + q];
        *(float4*)&sXS[p*E_STRIDE + q] = *(const float4*)&g_xs[p*NN + n0 + q];
    }

#pragma unroll
    for (int i = 0; i < 4; i++) {
        float z  = acc[i] + benc[n0 + nb + i];
        float p0 = TWO_PI_F / (1.0f + expf(-z));
        int gi = (r0+row)*NN + n0 + nb + i;
        g_phi[gi] = p0;
        float ss, cc;
        __sincosf(p0, &ss, &cc);
        g_fc[gi] = cc;
        g_fs[gi] = ss;
        sC[row*E_STRIDE + nb + i] = cc;
        sS[row*E_STRIDE + nb + i] = ss;
    }
    __syncthreads();
    m_tail_enc(sC, sS, sXC, sXS, g_m[0], r0);
}

/* ================= persistent RK4 kernel ================================ */
__global__ void __launch_bounds__(256, 2)
k_run(EvalConsts ec) {
    extern __shared__ float sm[];
    float* sW  = sm;
    float* sXC = sm + OFF_XC;
    float* sXS = sm + OFF_XS;
    float* sC  = sm + OFF_C;
    float* sS  = sm + OFF_S;
    float* sP  = sm + OFF_P;
    float* sA  = sm + OFF_A;
    float* sR  = sm + OFF_R;          /* K-half exchange: [256][8] */

    int n0 = blockIdx.x*CH, r0 = blockIdx.y*RPC;
    int tid = threadIdx.x;
    int warp = tid >> 5, lane = tid & 31;
    int cta = blockIdx.y*GXS + blockIdx.x;   /* 0..255 */
    int grp = blockIdx.y;

    /* coupling / elementwise mapping */
    int kh  = warp >> 2;               /* K half 0/1            */
    int wl  = warp & 3;
    int rp  = lane >> 2;               /* rowpair 0..7          */
    int cg  = wl*4 + (lane & 3);       /* colgroup 0..15        */
    int erow = rp*2 + kh;              /* elementwise row 0..15 */
    int so  = erow*SC_STRIDE + cg*4;
    int gso = (r0+erow)*NN + n0 + cg*4;

    /* ---- one-time loads ---- */
#pragma unroll
    for (int it = 0; it < 8; it++) {
        int i = tid + it*256;          /* 0..2047 quads */
        int p = i >> 4, q = (i & 15) << 2;
        CP16(su32(&sXC[p*SX_STRIDE + q]), &g_xc[p*NN + n0 + q]);
        CP16(su32(&sXS[p*SX_STRIDE + q]), &g_xs[p*NN + n0 + q]);
    }
    CP16(su32(&sC[so]), &g_fc[gso]);
    CP16(su32(&sS[so]), &g_fs[gso]);
    CP16(su32(&sP[so]), &g_phi[gso]);
    CP_COMMIT();
    CP_WAIT(0);
    __syncthreads();

    for (int e = 0; e < NEV; e++) {
        int sub  = e & 3;
        int bufR = e % 3, bufW = (e + 1) % 3, bufZ = (e + 2) % 3;
        float sAnc = ec.sA[e], cAnc = ec.cA[e], cNext = ec.cN[e];

        if (tid < 128) g_m[bufZ][cta*128 + tid] = 0.f;

        /* ---- softmax: row = tid>>4, 8 slots per thread; un-permute ---- */
        {
            int srow = tid >> 4, sp = tid & 15;
            const float* mrow = &g_m[bufR][(r0+srow)*PP + sp*8];
            float4 m0 = *(const float4*)&mrow[0];
            float4 m1 = *(const float4*)&mrow[4];
            float a[8];
            a[0]=__expf(m0.x*BETA_N); a[1]=__expf(m0.y*BETA_N);
            a[2]=__expf(m0.z*BETA_N); a[3]=__expf(m0.w*BETA_N);
            a[4]=__expf(m1.x*BETA_N); a[5]=__expf(m1.y*BETA_N);
            a[6]=__expf(m1.z*BETA_N); a[7]=__expf(m1.w*BETA_N);
            float ssum = 0.f;
#pragma unroll
            for (int k = 0; k < 8; k++) ssum += a[k];
#pragma unroll
            for (int w = 1; w < 16; w <<= 1)
                ssum += __shfl_xor_sync(0xffffffffu, ssum, w);
            float inv = 1.0f / ssum;
#pragma unroll
            for (int k = 0; k < 8; k++) {
                int s = sp*8 + k;
                int p = (s & 64) + ((s & 63) >> 2) + 16*(s & 3);
                sW[srow*SW_STRIDE + p] = a[k] * inv;
            }
        }
        __syncthreads();

        /* ---- coupling GEMM: tile 2r x 4c, K-half per thread ---- */
        ull c0a=0, c0b=0, c1a=0, c1b=0, s0a=0, s0b=0, s1a=0, s1b=0;
        {
            const float* w0  = &sW[(rp*2)*SW_STRIDE + kh*64];
            const float* w1  = w0 + SW_STRIDE;
            const float* xcB = &sXC[(kh*64)*SX_STRIDE + cg*4];
            const float* xsB = &sXS[(kh*64)*SX_STRIDE + cg*4];
#pragma unroll 4
            for (int p = 0; p < 64; p++) {
                ulonglong2 xc2 = *(const ulonglong2*)&xcB[p*SX_STRIDE];
                ulonglong2 xs2 = *(const ulonglong2*)&xsB[p*SX_STRIDE];
                float wa = w0[p], wb = w1[p];
                ull wpa = pack2(wa, wa), wpb = pack2(wb, wb);
                c0a = fma2(wpa, xc2.x, c0a); c0b = fma2(wpa, xc2.y, c0b);
                c1a = fma2(wpb, xc2.x, c1a); c1b = fma2(wpb, xc2.y, c1b);
                s0a = fma2(wpa, xs2.x, s0a); s0b = fma2(wpa, xs2.y, s0b);
                s1a = fma2(wpb, xs2.x, s1a); s1b = fma2(wpb, xs2.y, s1b);
            }
        }
        /* exchange: store partial for row kh^1, read partner (tid^128) */
        {
            ull otCa = kh ? c0a : c1a, otCb = kh ? c0b : c1b;
            ull otSa = kh ? s0a : s1a, otSb = kh ? s0b : s1b;
            ull* rr = (ull*)&sR[tid*8];
            rr[0] = otCa; rr[1] = otCb; rr[2] = otSa; rr[3] = otSb;
        }
        __syncthreads();

        /* ---- reduce + elementwise ---- */
        {
            const float* pr = &sR[(tid ^ 128)*8];
            float4 pc = *(const float4*)&pr[0];
            float4 psv = *(const float4*)&pr[4];
            ull myCa = kh ? c1a : c0a, myCb = kh ? c1b : c0b;
            ull mySa = kh ? s1a : s0a, mySb = kh ? s1b : s0b;
            float2 ua = unpk(myCa), ub = unpk(myCb);
            float2 va = unpk(mySa), vb = unpk(mySb);
            float wc4[4] = {ua.x + pc.x, ua.y + pc.y, ub.x + pc.z, ub.y + pc.w};
            float ws4[4] = {va.x + psv.x, va.y + psv.y, vb.x + psv.z, vb.y + psv.w};

            float4 fc = *(const float4*)&sC[so];
            float4 fs = *(const float4*)&sS[so];
            float ce[4] = {fc.x, fc.y, fc.z, fc.w};
            float se[4] = {fs.x, fs.y, fs.z, fs.w};
            float kv[4];
#pragma unroll
            for (int j = 0; j < 4; j++)
                kv[j] = fmaf(se[j], wc4[j] - cAnc, ce[j] * (sAnc - ws4[j]));

            float4 p0 = *(const float4*)&sP[so];
            float ph[4] = {p0.x, p0.y, p0.z, p0.w};
            float phiN[4];
            if (sub == 0) {
                *(float4*)&sA[so] = make_float4(kv[0], kv[1], kv[2], kv[3]);
#pragma unroll
                for (int j = 0; j < 4; j++) phiN[j] = fmaf(cNext, kv[j], ph[j]);
            } else if (sub == 3) {
                float4 a0 = *(const float4*)&sA[so];
                float av[4] = {a0.x, a0.y, a0.z, a0.w};
#pragma unroll
                for (int j = 0; j < 4; j++)
                    phiN[j] = fmaf(DT/6.0f, av[j] + kv[j], ph[j]);
                *(float4*)&sP[so] = make_float4(phiN[0], phiN[1], phiN[2], phiN[3]);
            } else {
                float4 a0 = *(const float4*)&sA[so];
                float av[4] = {a0.x, a0.y, a0.z, a0.w};
#pragma unroll
                for (int j = 0; j < 4; j++) av[j] = fmaf(2.0f, kv[j], av[j]);
                *(float4*)&sA[so] = make_float4(av[0], av[1], av[2], av[3]);
#pragma unroll
                for (int j = 0; j < 4; j++) phiN[j] = fmaf(cNext, kv[j], ph[j]);
            }

            if (e < NEV-1) {
                float cn[4], sn[4];
#pragma unroll
                for (int j = 0; j < 4; j++)
                    __sincosf(phiN[j], &sn[j], &cn[j]);
                *(float4*)&sC[so] = make_float4(cn[0], cn[1], cn[2], cn[3]);
                *(float4*)&sS[so] = make_float4(sn[0], sn[1], sn[2], sn[3]);
            }
        }

        if (e < NEV-1) {
            __syncthreads();
            /* ---- m_tail: warp = 4 rows x 64 pats; lane 2r x 4p; n=64.
               patterns p = phh*64 + pgl + 16j -> slots phh*64 + pgl*4 + j
               (contiguous) -> 2 atomicAdd(float4) per thread. ---- */
            {
                int rg  = warp >> 1;           /* 0..3: rows rg*4..+3 */
                int phh = warp & 1;            /* pattern half        */
                int rpl = lane >> 4;           /* rowpair in group    */
                int pgl = lane & 15;
                ull acc[8];
#pragma unroll
                for (int i = 0; i < 8; i++) acc[i] = 0ull;
                const float* cB  = sC + (rg*4 + rpl*2)*SC_STRIDE;
                const float* sB  = sS + (rg*4 + rpl*2)*SC_STRIDE;
                const float* xcB = &sXC[(phh*64 + pgl)*SX_STRIDE];
                const float* xsB = &sXS[(phh*64 + pgl)*SX_STRIDE];
#pragma unroll
                for (int nn = 0; nn < CH; nn += 4) {
                    ulonglong2 cr0 = *(const ulonglong2*)&cB[nn];
                    ulonglong2 cr1 = *(const ulonglong2*)&cB[SC_STRIDE + nn];
                    ulonglong2 sr0 = *(const ulonglong2*)&sB[nn];
                    ulonglong2 sr1 = *(const ulonglong2*)&sB[SC_STRIDE + nn];
#pragma unroll
                    for (int j = 0; j < 4; j++) {
                        ulonglong2 xc2 =
                            *(const ulonglong2*)&xcB[j*16*SX_STRIDE + nn];
                        ulonglong2 xs2 =
                            *(const ulonglong2*)&xsB[j*16*SX_STRIDE + nn];
                        ull a0 = acc[j*2], a1 = acc[j*2 + 1];
                        a0 = fma2(cr0.x, xc2.x, a0);
                        a0 = fma2(cr0.y, xc2.y, a0);
                        a0 = fma2(sr0.x, xs2.x, a0);
                        a0 = fma2(sr0.y, xs2.y, a0);
                        a1 = fma2(cr1.x, xc2.x, a1);
                        a1 = fma2(cr1.y, xc2.y, a1);
                        a1 = fma2(sr1.x, xs2.x, a1);
                        a1 = fma2(sr1.y, xs2.y, a1);
                        acc[j*2] = a0; acc[j*2 + 1] = a1;
                    }
                }
                float* mbuf = g_m[bufW];
                int rr = r0 + rg*4 + rpl*2;
                int sb = phh*64 + pgl*4;
                float4 v0 = make_float4(hadd2(acc[0]), hadd2(acc[2]),
                                        hadd2(acc[4]), hadd2(acc[6]));
                float4 v1 = make_float4(hadd2(acc[1]), hadd2(acc[3]),
                                        hadd2(acc[5]), hadd2(acc[7]));
                atomicAdd((float4*)&mbuf[rr*PP + sb],     v0);
                atomicAdd((float4*)&mbuf[(rr+1)*PP + sb], v1);
            }
            /* ---- group barrier: 16 CTAs ---- */
            __syncthreads();
            if (tid == 0) {
                __threadfence();
                atomicAdd(&g_cnt[grp*NEV + e], 1u);
                volatile unsigned* c = &g_cnt[grp*NEV + e];
                while (*c < (unsigned)GXS) { }
                __threadfence();
            }
            __syncthreads();
        }
    }

    *(float4*)&g_phi[gso] = *(const float4*)&sP[so];
}

/* ================= readout ============================================== */
__global__ void __launch_bounds__(256)
k_readout(const float* __restrict__ Wout,
          const float* __restrict__ bout,
          float* __restrict__ out) {
    __shared__ float red[8*2*COUT];
    int b0 = blockIdx.x*2, tid = threadIdx.x;
    int n4 = tid*4;

    float4 pa = *(const float4*)&g_phi[b0*NN + n4];
    float4 pb = *(const float4*)&g_phi[(b0+1)*NN + n4];
    float pha[4] = {pa.x, pa.y, pa.z, pa.w};
    float phb[4] = {pb.x, pb.y, pb.z, pb.w};
    float ca[4], sa[4], cb[4], sb[4];
#pragma unroll
    for (int j = 0; j < 4; j++) {
        sincosf(pha[j], &sa[j], &ca[j]);
        sincosf(phb[j], &sb[j], &cb[j]);
    }

    float acc[2][COUT];
#pragma unroll
    for (int cls = 0; cls < COUT; cls++) {
        float4 wcv = *(const float4*)&Wout[cls*(2*NN) + n4];
        float4 wsv = *(const float4*)&Wout[cls*(2*NN) + NN + n4];
        float a0 = ca[0]*wcv.x + sa[0]*wsv.x;
        a0 = fmaf(ca[1], wcv.y, a0); a0 = fmaf(sa[1], wsv.y, a0);
        a0 = fmaf(ca[2], wcv.z, a0); a0 = fmaf(sa[2], wsv.z, a0);
        a0 = fmaf(ca[3], wcv.w, a0); a0 = fmaf(sa[3], wsv.w, a0);
        acc[0][cls] = a0;
        float a1 = cb[0]*wcv.x + sb[0]*wsv.x;
        a1 = fmaf(cb[1], wcv.y, a1); a1 = fmaf(sb[1], wsv.y, a1);
        a1 = fmaf(cb[2], wcv.z, a1); a1 = fmaf(sb[2], wsv.z, a1);
        a1 = fmaf(cb[3], wcv.w, a1); a1 = fmaf(sb[3], wsv.w, a1);
        acc[1][cls] = a1;
    }
#pragma unroll
    for (int rr = 0; rr < 2; rr++)
#pragma unroll
        for (int cls = 0; cls < COUT; cls++)
#pragma unroll
            for (int w = 16; w > 0; w >>= 1)
                acc[rr][cls] += __shfl_xor_sync(0xffffffffu, acc[rr][cls], w);

    int warp = tid >> 5, lane = tid & 31;
    if (lane == 0)
#pragma unroll
        for (int rr = 0; rr < 2; rr++)
#pragma unroll
            for (int cls = 0; cls < COUT; cls++)
                red[warp*2*COUT + rr*COUT + cls] = acc[rr][cls];
    __syncthreads();

    if (tid < 2*COUT) {
        int rr = tid / COUT, cls = tid % COUT;
        float t = bout[cls];
#pragma unroll
        for (int w = 0; w < 8; w++) t += red[w*2*COUT + rr*COUT + cls];
        out[(b0+rr)*COUT + cls] = t;
    }
}

/* ================= host ================================================= */
extern "C" void kernel_launch(void* const* d_in, const int* in_sizes, int n_in,
                              void* d_out, int out_size) {
    (void)in_sizes; (void)n_in; (void)out_size;
    const float* x    = (const float*)d_in[0];
    const float* Wenc = (const float*)d_in[1];
    const float* benc = (const float*)d_in[2];
    const float* xi   = (const float*)d_in[3];
    const float* Wout = (const float*)d_in[4];
    const float* bout = (const float*)d_in[5];
    float* out = (float*)d_out;

    cudaFuncSetAttribute(k_encoder, cudaFuncAttributeMaxDynamicSharedMemorySize, SMEM_BYTES);
    cudaFuncSetAttribute(k_run,     cudaFuncAttributeMaxDynamicSharedMemorySize, SMEM_BYTES);

    EvalConsts ec;
    for (int e = 0; e < NEV; e++) {
        int step = e >> 2, sub = e & 3;
        float t0 = (float)step * DT;
        float tE = (sub == 0) ? t0 : ((sub == 3) ? t0 + DT : t0 + 0.5f*DT);
        float argf = OME * tE;
        double sa = sin((double)argf), ca = cos((double)argf);
        ec.sA[e] = (float)((double)A_ANC * sa);
        ec.cA[e] = (float)((double)A_ANC * ca);
        ec.cN[e] = (sub == 2) ? DT : 0.5f*DT;
    }

    k_init<<<512, 256>>>(xi);

    dim3 egrid(32, 8);
    k_encoder<<<egrid, 256, SMEM_BYTES>>>(x, Wenc, benc);

    dim3 rgrid(GXS, NGRP);           /* 16 x 16 = 256 CTAs, all resident */
    k_run<<<rgrid, 256, SMEM_BYTES>>>(ec);

    k_readout<<<BATCH/2, 256>>>(Wout, bout, out);
}

// round 15
// speedup vs baseline: 1.1717x; 1.1717x over previous
#include <cuda_runtime.h>
#include <math.h>

#define BATCH 256
#define NN    1024
#define PP    128
#define DIN   784
#define COUT  10
#define CH    32                     /* columns per CTA */
#define NEV   64                     /* RK4 evals */
#define NGRP  8                      /* row groups (blockIdx.y) */
#define GXS   32                     /* CTAs per group (blockIdx.x) */

#define TWO_PI_F 6.283185307179586f
#define DT       0.03125f
#define BETA_N   (2.0f/1024.0f)
#define A_ANC    0.08f
#define OME      (TWO_PI_F*200.0f)

typedef unsigned long long ull;

__device__ __forceinline__ ull pack2(float a, float b) {
    ull r; asm("mov.b64 %0,{%1,%2};" : "=l"(r) : "f"(a), "f"(b)); return r;
}
__device__ __forceinline__ ull fma2(ull a, ull b, ull c) {
    ull d; asm("fma.rn.f32x2 %0,%1,%2,%3;" : "=l"(d) : "l"(a), "l"(b), "l"(c));
    return d;
}
__device__ __forceinline__ float hadd2(ull a) {
    float lo, hi;
    asm("mov.b64 {%0,%1},%2;" : "=f"(lo), "=f"(hi) : "l"(a));
    return lo + hi;
}
__device__ __forceinline__ unsigned su32(const void* p) {
    return (unsigned)__cvta_generic_to_shared(p);
}
#define CP16(dst, src) \
    asm volatile("cp.async.cg.shared.global [%0], [%1], 16;" :: "r"(dst), "l"(src))
#define CP_COMMIT() asm volatile("cp.async.commit_group;")
#define CP_WAIT(n)  asm volatile("cp.async.wait_group %0;" :: "n"(n))

/* m slot permutation: pattern p = pb + 32j (pb in [0,32), j in [0,4))
   lives at slot pb*4 + j -> each m_tail thread's 4 partials per row are
   CONTIGUOUS -> one atomicAdd(float4). Inverse: p(s) = (s>>2) + 32*(s&3). */

struct EvalConsts { float sA[NEV]; float cA[NEV]; float cN[NEV]; };

/* ---- device scratch ---- */
__device__ float g_xc[PP*NN];
__device__ float g_xs[PP*NN];
__device__ float g_phi[BATCH*NN];
__device__ float g_fc[BATCH*NN];
__device__ float g_fs[BATCH*NN];
__device__ float g_m[3][BATCH*PP];   /* permuted slot layout */
__device__ unsigned g_cnt[NGRP*NEV];

/* ---- shared layout (floats) ---- */
#define SW_STRIDE 130
#define SX_STRIDE 36
#define SC_STRIDE 36
#define SR_STRIDE 36
#define SW_FLOATS (32*SW_STRIDE)
#define SX_FLOATS (128*SX_STRIDE)
#define SC_FLOATS (32*SC_STRIDE)
#define SR_FLOATS (256*SR_STRIDE)
#define SMEM_FLOATS (SW_FLOATS + 2*SX_FLOATS + 4*SC_FLOATS + SR_FLOATS)
#define SMEM_BYTES  (SMEM_FLOATS*4)  /* 108800 -> 2 CTAs/SM */

/* ================= init ================================================= */
__global__ void k_init(const float* __restrict__ xi) {
    int i = blockIdx.x*256 + threadIdx.x;
    if (i < PP*NN) {
        float v = xi[i];
        g_xc[i] = cosf(v);
        g_xs[i] = sinf(v);
    }
    if (i < BATCH*PP) { g_m[0][i] = 0.f; g_m[1][i] = 0.f; }
    if (i < NGRP*NEV) g_cnt[i] = 0u;
}

__device__ __forceinline__ void load_xtiles(float* sXC, float* sXS, int n0) {
    for (int i = threadIdx.x; i < 128*8; i += 256) {
        int p = i >> 3, q = (i & 7) << 2;
        float4 a = *(const float4*)&g_xc[p*NN + n0 + q];
        *(float4*)&sXC[p*SX_STRIDE + q] = a;
        float4 b = *(const float4*)&g_xs[p*NN + n0 + q];
        *(float4*)&sXS[p*SX_STRIDE + q] = b;
    }
}

/* partial m over this CTA's 32-col chunk; fma2, 4 rows x 4 patterns;
   permuted slots -> ONE float4 atomic per row (4 total, RED.v4 path). */
__device__ __forceinline__ void m_tail(const float* sC, const float* sS,
                                       const float* sXC, const float* sXS,
                                       float* mbuf, int r0) {
    int rb = threadIdx.x >> 5;       /* 0..7 -> rows rb*4..rb*4+3 */
    int pb = threadIdx.x & 31;       /* pats pb + 32*j            */
    ull acc[16];
#pragma unroll
    for (int i = 0; i < 16; i++) acc[i] = 0ull;
    const float* cB  = sC  + (rb*4)*SC_STRIDE;
    const float* sB  = sS  + (rb*4)*SC_STRIDE;
    const float* xcB = sXC + pb*SX_STRIDE;
    const float* xsB = sXS + pb*SX_STRIDE;
#pragma unroll
    for (int nn = 0; nn < CH; nn += 4) {
        ulonglong2 cr[4], sr[4];
#pragma unroll
        for (int r = 0; r < 4; r++) {
            cr[r] = *(const ulonglong2*)&cB[r*SC_STRIDE + nn];
            sr[r] = *(const ulonglong2*)&sB[r*SC_STRIDE + nn];
        }
#pragma unroll
        for (int j = 0; j < 4; j++) {
            ulonglong2 xc2 = *(const ulonglong2*)&xcB[j*32*SX_STRIDE + nn];
            ulonglong2 xs2 = *(const ulonglong2*)&xsB[j*32*SX_STRIDE + nn];
#pragma unroll
            for (int r = 0; r < 4; r++) {
                ull a = acc[j*4 + r];
                a = fma2(cr[r].x, xc2.x, a);
                a = fma2(cr[r].y, xc2.y, a);
                a = fma2(sr[r].x, xs2.x, a);
                a = fma2(sr[r].y, xs2.y, a);
                acc[j*4 + r] = a;
            }
        }
    }
#pragma unroll
    for (int r = 0; r < 4; r++) {
        float4 v = make_float4(hadd2(acc[0*4 + r]), hadd2(acc[1*4 + r]),
                               hadd2(acc[2*4 + r]), hadd2(acc[3*4 + r]));
        atomicAdd((float4*)&mbuf[(r0 + rb*4 + r)*PP + pb*4], v);
    }
}

/* ================= encoder ============================================== */
__global__ void __launch_bounds__(256, 2)
k_encoder(const float* __restrict__ x,
          const float* __restrict__ Wenc,
          const float* __restrict__ benc) {
    extern __shared__ float sm[];
    float* sA  = sm;
    float* sB  = sm + 32*17;
    float* sXC = sm + SW_FLOATS;
    float* sXS = sXC + SX_FLOATS;
    float* sC  = sXS + SX_FLOATS;
    float* sS  = sC + SC_FLOATS;

    int n0 = blockIdx.x*CH, r0 = blockIdx.y*32;
    int tid = threadIdx.x;
    int row = tid >> 3, ng = tid & 7, nb = ng*4;

    float acc[4];
#pragma unroll
    for (int i = 0; i < 4; i++) acc[i] = 0.f;

    for (int d0 = 0; d0 < DIN; d0 += 16) {
        for (int i = tid; i < 512; i += 256) {
            int r = i >> 4, j = i & 15;
            sA[r*17 + j] = x[(r0+r)*DIN + d0 + j];
            sB[r*17 + j] = Wenc[(n0+r)*DIN + d0 + j];
        }
        __syncthreads();
#pragma unroll
        for (int j = 0; j < 16; j++) {
            float xa = sA[row*17 + j];
#pragma unroll
            for (int i = 0; i < 4; i++) acc[i] += xa * sB[(nb+i)*17 + j];
        }
        __syncthreads();
    }

    load_xtiles(sXC, sXS, n0);

#pragma unroll
    for (int i = 0; i < 4; i++) {
        float z  = acc[i] + benc[n0 + nb + i];
        float p0 = TWO_PI_F / (1.0f + expf(-z));
        int gi = (r0+row)*NN + n0 + nb + i;
        g_phi[gi]  = p0;
        float ss, cc;
        __sincosf(p0, &ss, &cc);
        g_fc[gi] = cc;
        g_fs[gi] = ss;
        sC[row*SC_STRIDE + nb + i] = cc;
        sS[row*SC_STRIDE + nb + i] = ss;
    }
    __syncthreads();
    m_tail(sC, sS, sXC, sXS, g_m[0], r0);
}

/* ================= persistent RK4 kernel ================================ */
__global__ void __launch_bounds__(256, 2)
k_run(EvalConsts ec) {
    extern __shared__ float sm[];
    float* sW  = sm;
    float* sXC = sm + SW_FLOATS;
    float* sXS = sXC + SX_FLOATS;
    float* sC  = sXS + SX_FLOATS;
    float* sS  = sC + SC_FLOATS;
    float* sP  = sS + SC_FLOATS;
    float* sA  = sP + SC_FLOATS;
    float* sR  = sA + SC_FLOATS;

    int n0 = blockIdx.x*CH, r0 = blockIdx.y*32;
    int tid = threadIdx.x;
    int row = tid >> 3, cf = tid & 7;
    int so  = row*SC_STRIDE + cf*4;
    int gso = (r0+row)*NN + n0 + cf*4;
    int cta = blockIdx.y*GXS + blockIdx.x;
    int grp = blockIdx.y;

    /* ---- one-time loads: xi tiles + state ---- */
#pragma unroll
    for (int it = 0; it < 4; it++) {
        int i = tid + it*256;
        int p = i >> 3, q = (i & 7) << 2;
        CP16(su32(&sXC[p*SX_STRIDE + q]), &g_xc[p*NN + n0 + q]);
        CP16(su32(&sXS[p*SX_STRIDE + q]), &g_xs[p*NN + n0 + q]);
    }
    CP16(su32(&sC[so]), &g_fc[gso]);
    CP16(su32(&sS[so]), &g_fs[gso]);
    CP16(su32(&sP[so]), &g_phi[gso]);
    CP_COMMIT();

    for (int e = 0; e < NEV; e++) {
        int sub  = e & 3;
        int bufR = e % 3, bufW = (e + 1) % 3, bufZ = (e + 2) % 3;
        float sAnc = ec.sA[e], cAnc = ec.cA[e], cNext = ec.cN[e];

        /* prefetch m slot slice for this eval */
        {
            const float* gmp = &g_m[bufR][(r0+row)*PP + cf*16];
            unsigned d = su32(&sR[row*PP + cf*16]);
            CP16(d,      gmp);
            CP16(d + 16, gmp + 4);
            CP16(d + 32, gmp + 8);
            CP16(d + 48, gmp + 12);
        }
        CP_COMMIT();

        /* zero the buffer used two evals ahead (own group rows only) */
        if (tid < 128) g_m[bufZ][cta*128 + tid] = 0.f;

        CP_WAIT(0);
        /* ---- softmax (arg in [-2,2]); un-permute slots on sW write ---- */
        {
            const float* mrow = &sR[row*PP + cf*16];
            float a[16];
            float ssum = 0.f;
#pragma unroll
            for (int j = 0; j < 16; j++) {
                a[j] = __expf(mrow[j] * BETA_N);
                ssum += a[j];
            }
#pragma unroll
            for (int w = 1; w < 8; w <<= 1)
                ssum += __shfl_xor_sync(0xffffffffu, ssum, w);
            float inv = 1.0f / ssum;
#pragma unroll
            for (int j = 0; j < 16; j++) {
                int s = cf*16 + j;
                int p = (s >> 2) + 32*(s & 3);
                sW[row*SW_STRIDE + p] = a[j] * inv;
            }
        }
        __syncthreads();

        /* ---- coupling GEMM, tile 4 rows x 4 cols (f32x2), K-split 4 ---- */
        {
            int ks   = tid >> 6;
            int r6   = tid & 63;
            int rowg = r6 >> 3;
            int colg = r6 & 7;
            ull aC0[4], aC1[4], aS0[4], aS1[4];
#pragma unroll
            for (int i = 0; i < 4; i++) { aC0[i]=0ull; aC1[i]=0ull; aS0[i]=0ull; aS1[i]=0ull; }
            const float* wB  = &sW[(rowg*4)*SW_STRIDE + ks*32];
            const float* xcB = &sXC[(ks*32)*SX_STRIDE + colg*4];
            const float* xsB = &sXS[(ks*32)*SX_STRIDE + colg*4];
#pragma unroll 4
            for (int p = 0; p < 32; p++) {
                ulonglong2 cp = *(const ulonglong2*)&xcB[p*SX_STRIDE];
                ulonglong2 spv = *(const ulonglong2*)&xsB[p*SX_STRIDE];
#pragma unroll
                for (int i = 0; i < 4; i++) {
                    float wv = wB[i*SW_STRIDE + p];
                    ull wp = pack2(wv, wv);
                    aC0[i] = fma2(wp, cp.x,  aC0[i]);
                    aC1[i] = fma2(wp, cp.y,  aC1[i]);
                    aS0[i] = fma2(wp, spv.x, aS0[i]);
                    aS1[i] = fma2(wp, spv.y, aS1[i]);
                }
            }
            float* rr = &sR[tid*SR_STRIDE];
#pragma unroll
            for (int i = 0; i < 4; i++) {
                *(ull*)&rr[i*4]        = aC0[i];
                *(ull*)&rr[i*4 + 2]    = aC1[i];
                *(ull*)&rr[16 + i*4]   = aS0[i];
                *(ull*)&rr[16 + i*4+2] = aS1[i];
            }
        }
        __syncthreads();

        /* ---- reduce + elementwise: all 256 threads, 4 cols each ---- */
        {
            int wr = ((row >> 2) << 3) + cf;
            int ib = (row & 3) * 4;
            float wc4[4] = {0.f, 0.f, 0.f, 0.f};
            float ws4[4] = {0.f, 0.f, 0.f, 0.f};
#pragma unroll
            for (int ksr = 0; ksr < 4; ksr++) {
                const float* r = &sR[(ksr*64 + wr)*SR_STRIDE];
                float4 c4 = *(const float4*)&r[ib];
                float4 s4 = *(const float4*)&r[16 + ib];
                wc4[0] += c4.x; wc4[1] += c4.y; wc4[2] += c4.z; wc4[3] += c4.w;
                ws4[0] += s4.x; ws4[1] += s4.y; ws4[2] += s4.z; ws4[3] += s4.w;
            }

            float4 fc = *(const float4*)&sC[so];
            float4 fs = *(const float4*)&sS[so];
            float ce[4] = {fc.x, fc.y, fc.z, fc.w};
            float se[4] = {fs.x, fs.y, fs.z, fs.w};
            float kv[4];
#pragma unroll
            for (int j = 0; j < 4; j++)
                kv[j] = fmaf(se[j], wc4[j] - cAnc, ce[j] * (sAnc - ws4[j]));

            float4 p0 = *(const float4*)&sP[so];
            float ph[4] = {p0.x, p0.y, p0.z, p0.w};
            float phiN[4];
            if (sub == 0) {
                *(float4*)&sA[so] = make_float4(kv[0], kv[1], kv[2], kv[3]);
#pragma unroll
                for (int j = 0; j < 4; j++) phiN[j] = fmaf(cNext, kv[j], ph[j]);
            } else if (sub == 3) {
                float4 a0 = *(const float4*)&sA[so];
                float av[4] = {a0.x, a0.y, a0.z, a0.w};
#pragma unroll
                for (int j = 0; j < 4; j++)
                    phiN[j] = fmaf(DT/6.0f, av[j] + kv[j], ph[j]);
                *(float4*)&sP[so] = make_float4(phiN[0], phiN[1], phiN[2], phiN[3]);
            } else {
                float4 a0 = *(const float4*)&sA[so];
                float av[4] = {a0.x, a0.y, a0.z, a0.w};
#pragma unroll
                for (int j = 0; j < 4; j++) av[j] = fmaf(2.0f, kv[j], av[j]);
                *(float4*)&sA[so] = make_float4(av[0], av[1], av[2], av[3]);
#pragma unroll
                for (int j = 0; j < 4; j++) phiN[j] = fmaf(cNext, kv[j], ph[j]);
            }

            if (e < NEV-1) {
                float cn[4], sn[4];
#pragma unroll
                for (int j = 0; j < 4; j++)
                    __sincosf(phiN[j], &sn[j], &cn[j]);
                *(float4*)&sC[so] = make_float4(cn[0], cn[1], cn[2], cn[3]);
                *(float4*)&sS[so] = make_float4(sn[0], sn[1], sn[2], sn[3]);
            }
        }

        if (e < NEV-1) {
            __syncthreads();
            m_tail(sC, sS, sXC, sXS, g_m[bufW], r0);
            /* ---- group barrier: 32 CTAs of this row group ---- */
            __syncthreads();
            if (tid == 0) {
                __threadfence();
                atomicAdd(&g_cnt[grp*NEV + e], 1u);
                volatile unsigned* c = &g_cnt[grp*NEV + e];
                while (*c < (unsigned)GXS) { }
                __threadfence();
            }
            __syncthreads();
        }
    }

    *(float4*)&g_phi[gso] = *(const float4*)&sP[so];
}

/* ================= readout ============================================== */
__global__ void __launch_bounds__(256)
k_readout(const float* __restrict__ Wout,
          const float* __restrict__ bout,
          float* __restrict__ out) {
    __shared__ float red[8*2*COUT];
    int b0 = blockIdx.x*2, tid = threadIdx.x;
    int n4 = tid*4;

    float4 pa = *(const float4*)&g_phi[b0*NN + n4];
    float4 pb = *(const float4*)&g_phi[(b0+1)*NN + n4];
    float pha[4] = {pa.x, pa.y, pa.z, pa.w};
    float phb[4] = {pb.x, pb.y, pb.z, pb.w};
    float ca[4], sa[4], cb[4], sb[4];
#pragma unroll
    for (int j = 0; j < 4; j++) {
        sincosf(pha[j], &sa[j], &ca[j]);
        sincosf(phb[j], &sb[j], &cb[j]);
    }

    float acc[2][COUT];
#pragma unroll
    for (int cls = 0; cls < COUT; cls++) {
        float4 wcv = *(const float4*)&Wout[cls*(2*NN) + n4];
        float4 wsv = *(const float4*)&Wout[cls*(2*NN) + NN + n4];
        float a0 = ca[0]*wcv.x + sa[0]*wsv.x;
        a0 = fmaf(ca[1], wcv.y, a0); a0 = fmaf(sa[1], wsv.y, a0);
        a0 = fmaf(ca[2], wcv.z, a0); a0 = fmaf(sa[2], wsv.z, a0);
        a0 = fmaf(ca[3], wcv.w, a0); a0 = fmaf(sa[3], wsv.w, a0);
        acc[0][cls] = a0;
        float a1 = cb[0]*wcv.x + sb[0]*wsv.x;
        a1 = fmaf(cb[1], wcv.y, a1); a1 = fmaf(sb[1], wsv.y, a1);
        a1 = fmaf(cb[2], wcv.z, a1); a1 = fmaf(sb[2], wsv.z, a1);
        a1 = fmaf(cb[3], wcv.w, a1); a1 = fmaf(sb[3], wsv.w, a1);
        acc[1][cls] = a1;
    }
#pragma unroll
    for (int rr = 0; rr < 2; rr++)
#pragma unroll
        for (int cls = 0; cls < COUT; cls++)
#pragma unroll
            for (int w = 16; w > 0; w >>= 1)
                acc[rr][cls] += __shfl_xor_sync(0xffffffffu, acc[rr][cls], w);

    int warp = tid >> 5, lane = tid & 31;
    if (lane == 0)
#pragma unroll
        for (int rr = 0; rr < 2; rr++)
#pragma unroll
            for (int cls = 0; cls < COUT; cls++)
                red[warp*2*COUT + rr*COUT + cls] = acc[rr][cls];
    __syncthreads();

    if (tid < 2*COUT) {
        int rr = tid / COUT, cls = tid % COUT;
        float t = bout[cls];
#pragma unroll
        for (int w = 0; w < 8; w++) t += red[w*2*COUT + rr*COUT + cls];
        out[(b0+rr)*COUT + cls] = t;
    }
}

/* ================= host ================================================= */
extern "C" void kernel_launch(void* const* d_in, const int* in_sizes, int n_in,
                              void* d_out, int out_size) {
    (void)in_sizes; (void)n_in; (void)out_size;
    const float* x    = (const float*)d_in[0];
    const float* Wenc = (const float*)d_in[1];
    const float* benc = (const float*)d_in[2];
    const float* xi   = (const float*)d_in[3];
    const float* Wout = (const float*)d_in[4];
    const float* bout = (const float*)d_in[5];
    float* out = (float*)d_out;

    cudaFuncSetAttribute(k_encoder, cudaFuncAttributeMaxDynamicSharedMemorySize, SMEM_BYTES);
    cudaFuncSetAttribute(k_run,     cudaFuncAttributeMaxDynamicSharedMemorySize, SMEM_BYTES);

    EvalConsts ec;
    for (int e = 0; e < NEV; e++) {
        int step = e >> 2, sub = e & 3;
        float t0 = (float)step * DT;
        float tE = (sub == 0) ? t0 : ((sub == 3) ? t0 + DT : t0 + 0.5f*DT);
        float argf = OME * tE;
        double sa = sin((double)argf), ca = cos((double)argf);
        ec.sA[e] = (float)((double)A_ANC * sa);
        ec.cA[e] = (float)((double)A_ANC * ca);
        ec.cN[e] = (sub == 2) ? DT : 0.5f*DT;
    }

    k_init<<<512, 256>>>(xi);

    dim3 grid(GXS, NGRP);            /* 32 x 8 = 256 CTAs, all resident */
    k_encoder<<<grid, 256, SMEM_BYTES>>>(x, Wenc, benc);
    k_run<<<grid, 256, SMEM_BYTES>>>(ec);
    k_readout<<<BATCH/2, 256>>>(Wout, bout, out);
}

// round 16
// speedup vs baseline: 1.1988x; 1.0232x over previous
#include <cuda_runtime.h>
#include <math.h>

#define BATCH 256
#define NN    1024
#define PP    128
#define DIN   784
#define COUT  10
#define CH    32                     /* columns per CTA */
#define NEV   64                     /* RK4 evals */
#define NGRP  8                      /* row groups (blockIdx.y) */
#define GXS   32                     /* CTAs per group (blockIdx.x) */

#define TWO_PI_F 6.283185307179586f
#define DT       0.03125f
#define BETA_N   (2.0f/1024.0f)
#define A_ANC    0.08f
#define OME      (TWO_PI_F*200.0f)

typedef unsigned long long ull;

__device__ __forceinline__ ull pack2(float a, float b) {
    ull r; asm("mov.b64 %0,{%1,%2};" : "=l"(r) : "f"(a), "f"(b)); return r;
}
__device__ __forceinline__ ull fma2(ull a, ull b, ull c) {
    ull d; asm("fma.rn.f32x2 %0,%1,%2,%3;" : "=l"(d) : "l"(a), "l"(b), "l"(c));
    return d;
}
__device__ __forceinline__ float hadd2(ull a) {
    float lo, hi;
    asm("mov.b64 {%0,%1},%2;" : "=f"(lo), "=f"(hi) : "l"(a));
    return lo + hi;
}
__device__ __forceinline__ unsigned su32(const void* p) {
    return (unsigned)__cvta_generic_to_shared(p);
}
#define CP16(dst, src) \
    asm volatile("cp.async.cg.shared.global [%0], [%1], 16;" :: "r"(dst), "l"(src))
#define CP_COMMIT() asm volatile("cp.async.commit_group;")
#define CP_WAIT(n)  asm volatile("cp.async.wait_group %0;" :: "n"(n))

/* m slot permutation: pattern p = pb + 32j stored at slot pb*4 + j ->
   each m_tail thread's 4 partials per row are CONTIGUOUS -> one
   atomicAdd(float4). Inverse: p(s) = (s>>2) + 32*(s&3). */

struct EvalConsts { float sA[NEV]; float cA[NEV]; float cN[NEV]; };

/* ---- device scratch ---- */
__device__ float g_xc[PP*NN];
__device__ float g_xs[PP*NN];
__device__ float g_phi[BATCH*NN];
__device__ float g_fc[BATCH*NN];
__device__ float g_fs[BATCH*NN];
__device__ float g_m[3][BATCH*PP];   /* permuted slot layout */
__device__ unsigned g_cnt[NGRP*NEV];

/* ---- shared layout (floats) ---- */
#define SW_STRIDE 130
#define SX_STRIDE 36
#define SC_STRIDE 36
#define SR_STRIDE 36
#define SW_FLOATS (32*SW_STRIDE)
#define SX_FLOATS (128*SX_STRIDE)
#define SC_FLOATS (32*SC_STRIDE)
#define SR_FLOATS (256*SR_STRIDE)
#define SMEM_FLOATS (SW_FLOATS + 2*SX_FLOATS + 4*SC_FLOATS + SR_FLOATS)
#define SMEM_BYTES  (SMEM_FLOATS*4)  /* 108800 -> 2 CTAs/SM */

/* ================= init: trig tables, m bufs, counters, out=bias ======== */
__global__ void k_init(const float* __restrict__ xi,
                       const float* __restrict__ bout,
                       float* __restrict__ out) {
    int i = blockIdx.x*256 + threadIdx.x;
    if (i < PP*NN) {
        float v = xi[i];
        g_xc[i] = cosf(v);
        g_xs[i] = sinf(v);
    }
    if (i < BATCH*PP) { g_m[0][i] = 0.f; g_m[1][i] = 0.f; }
    if (i < NGRP*NEV) g_cnt[i] = 0u;
    if (i < BATCH*COUT) out[i] = bout[i % COUT];
}

__device__ __forceinline__ void load_xtiles(float* sXC, float* sXS, int n0) {
    for (int i = threadIdx.x; i < 128*8; i += 256) {
        int p = i >> 3, q = (i & 7) << 2;
        float4 a = *(const float4*)&g_xc[p*NN + n0 + q];
        *(float4*)&sXC[p*SX_STRIDE + q] = a;
        float4 b = *(const float4*)&g_xs[p*NN + n0 + q];
        *(float4*)&sXS[p*SX_STRIDE + q] = b;
    }
}

/* partial m over this CTA's 32-col chunk; fma2, 4 rows x 4 patterns;
   permuted slots -> ONE float4 atomic per row (4 total, RED.v4 path). */
__device__ __forceinline__ void m_tail(const float* sC, const float* sS,
                                       const float* sXC, const float* sXS,
                                       float* mbuf, int r0) {
    int rb = threadIdx.x >> 5;
    int pb = threadIdx.x & 31;
    ull acc[16];
#pragma unroll
    for (int i = 0; i < 16; i++) acc[i] = 0ull;
    const float* cB  = sC  + (rb*4)*SC_STRIDE;
    const float* sB  = sS  + (rb*4)*SC_STRIDE;
    const float* xcB = sXC + pb*SX_STRIDE;
    const float* xsB = sXS + pb*SX_STRIDE;
#pragma unroll
    for (int nn = 0; nn < CH; nn += 4) {
        ulonglong2 cr[4], sr[4];
#pragma unroll
        for (int r = 0; r < 4; r++) {
            cr[r] = *(const ulonglong2*)&cB[r*SC_STRIDE + nn];
            sr[r] = *(const ulonglong2*)&sB[r*SC_STRIDE + nn];
        }
#pragma unroll
        for (int j = 0; j < 4; j++) {
            ulonglong2 xc2 = *(const ulonglong2*)&xcB[j*32*SX_STRIDE + nn];
            ulonglong2 xs2 = *(const ulonglong2*)&xsB[j*32*SX_STRIDE + nn];
#pragma unroll
            for (int r = 0; r < 4; r++) {
                ull a = acc[j*4 + r];
                a = fma2(cr[r].x, xc2.x, a);
                a = fma2(cr[r].y, xc2.y, a);
                a = fma2(sr[r].x, xs2.x, a);
                a = fma2(sr[r].y, xs2.y, a);
                acc[j*4 + r] = a;
            }
        }
    }
#pragma unroll
    for (int r = 0; r < 4; r++) {
        float4 v = make_float4(hadd2(acc[0*4 + r]), hadd2(acc[1*4 + r]),
                               hadd2(acc[2*4 + r]), hadd2(acc[3*4 + r]));
        atomicAdd((float4*)&mbuf[(r0 + rb*4 + r)*PP + pb*4], v);
    }
}

/* ================= encoder ============================================== */
__global__ void __launch_bounds__(256, 2)
k_encoder(const float* __restrict__ x,
          const float* __restrict__ Wenc,
          const float* __restrict__ benc) {
    extern __shared__ float sm[];
    float* sA  = sm;
    float* sB  = sm + 32*17;
    float* sXC = sm + SW_FLOATS;
    float* sXS = sXC + SX_FLOATS;
    float* sC  = sXS + SX_FLOATS;
    float* sS  = sC + SC_FLOATS;

    int n0 = blockIdx.x*CH, r0 = blockIdx.y*32;
    int tid = threadIdx.x;
    int row = tid >> 3, ng = tid & 7, nb = ng*4;

    float acc[4];
#pragma unroll
    for (int i = 0; i < 4; i++) acc[i] = 0.f;

    for (int d0 = 0; d0 < DIN; d0 += 16) {
        for (int i = tid; i < 512; i += 256) {
            int r = i >> 4, j = i & 15;
            sA[r*17 + j] = x[(r0+r)*DIN + d0 + j];
            sB[r*17 + j] = Wenc[(n0+r)*DIN + d0 + j];
        }
        __syncthreads();
#pragma unroll
        for (int j = 0; j < 16; j++) {
            float xa = sA[row*17 + j];
#pragma unroll
            for (int i = 0; i < 4; i++) acc[i] += xa * sB[(nb+i)*17 + j];
        }
        __syncthreads();
    }

    load_xtiles(sXC, sXS, n0);

#pragma unroll
    for (int i = 0; i < 4; i++) {
        float z  = acc[i] + benc[n0 + nb + i];
        float p0 = TWO_PI_F / (1.0f + expf(-z));
        int gi = (r0+row)*NN + n0 + nb + i;
        g_phi[gi]  = p0;
        float ss, cc;
        __sincosf(p0, &ss, &cc);
        g_fc[gi] = cc;
        g_fs[gi] = ss;
        sC[row*SC_STRIDE + nb + i] = cc;
        sS[row*SC_STRIDE + nb + i] = ss;
    }
    __syncthreads();
    m_tail(sC, sS, sXC, sXS, g_m[0], r0);
}

/* ================= persistent RK4 kernel + fused readout ================ */
__global__ void __launch_bounds__(256, 2)
k_run(EvalConsts ec, const float* __restrict__ Wout, float* __restrict__ out) {
    extern __shared__ float sm[];
    float* sW  = sm;
    float* sXC = sm + SW_FLOATS;
    float* sXS = sXC + SX_FLOATS;
    float* sC  = sXS + SX_FLOATS;
    float* sS  = sC + SC_FLOATS;
    float* sP  = sS + SC_FLOATS;
    float* sA  = sP + SC_FLOATS;
    float* sR  = sA + SC_FLOATS;

    int n0 = blockIdx.x*CH, r0 = blockIdx.y*32;
    int tid = threadIdx.x;
    int row = tid >> 3, cf = tid & 7;
    int so  = row*SC_STRIDE + cf*4;
    int gso = (r0+row)*NN + n0 + cf*4;
    int cta = blockIdx.y*GXS + blockIdx.x;
    int grp = blockIdx.y;

    /* ---- one-time loads: xi tiles + state ---- */
#pragma unroll
    for (int it = 0; it < 4; it++) {
        int i = tid + it*256;
        int p = i >> 3, q = (i & 7) << 2;
        CP16(su32(&sXC[p*SX_STRIDE + q]), &g_xc[p*NN + n0 + q]);
        CP16(su32(&sXS[p*SX_STRIDE + q]), &g_xs[p*NN + n0 + q]);
    }
    CP16(su32(&sC[so]), &g_fc[gso]);
    CP16(su32(&sS[so]), &g_fs[gso]);
    CP16(su32(&sP[so]), &g_phi[gso]);
    CP_COMMIT();
    CP_WAIT(0);
    __syncthreads();

    for (int e = 0; e < NEV; e++) {
        int sub  = e & 3;
        int bufR = e % 3, bufW = (e + 1) % 3, bufZ = (e + 2) % 3;
        float sAnc = ec.sA[e], cAnc = ec.cA[e], cNext = ec.cN[e];

        /* m slot slice: direct LDG into registers (issued early) */
        float mv[16];
        {
            const float* gmp = &g_m[bufR][(r0+row)*PP + cf*16];
            float4 a0 = *(const float4*)&gmp[0];
            float4 a1 = *(const float4*)&gmp[4];
            float4 a2 = *(const float4*)&gmp[8];
            float4 a3 = *(const float4*)&gmp[12];
            mv[0]=a0.x;  mv[1]=a0.y;  mv[2]=a0.z;  mv[3]=a0.w;
            mv[4]=a1.x;  mv[5]=a1.y;  mv[6]=a1.z;  mv[7]=a1.w;
            mv[8]=a2.x;  mv[9]=a2.y;  mv[10]=a2.z; mv[11]=a2.w;
            mv[12]=a3.x; mv[13]=a3.y; mv[14]=a3.z; mv[15]=a3.w;
        }

        /* zero the buffer used two evals ahead (own group rows only) */
        if (tid < 128) g_m[bufZ][cta*128 + tid] = 0.f;

        /* ---- softmax (arg in [-2,2]); un-permute slots on sW write ---- */
        {
            float a[16];
            float ssum = 0.f;
#pragma unroll
            for (int j = 0; j < 16; j++) {
                a[j] = __expf(mv[j] * BETA_N);
                ssum += a[j];
            }
#pragma unroll
            for (int w = 1; w < 8; w <<= 1)
                ssum += __shfl_xor_sync(0xffffffffu, ssum, w);
            float inv = 1.0f / ssum;
#pragma unroll
            for (int j = 0; j < 16; j++) {
                int s = cf*16 + j;
                int p = (s >> 2) + 32*(s & 3);
                sW[row*SW_STRIDE + p] = a[j] * inv;
            }
        }
        __syncthreads();

        /* ---- coupling GEMM, tile 4 rows x 4 cols (f32x2), K-split 4 ---- */
        {
            int ks   = tid >> 6;
            int r6   = tid & 63;
            int rowg = r6 >> 3;
            int colg = r6 & 7;
            ull aC0[4], aC1[4], aS0[4], aS1[4];
#pragma unroll
            for (int i = 0; i < 4; i++) { aC0[i]=0ull; aC1[i]=0ull; aS0[i]=0ull; aS1[i]=0ull; }
            const float* wB  = &sW[(rowg*4)*SW_STRIDE + ks*32];
            const float* xcB = &sXC[(ks*32)*SX_STRIDE + colg*4];
            const float* xsB = &sXS[(ks*32)*SX_STRIDE + colg*4];
#pragma unroll 4
            for (int p = 0; p < 32; p++) {
                ulonglong2 cp = *(const ulonglong2*)&xcB[p*SX_STRIDE];
                ulonglong2 spv = *(const ulonglong2*)&xsB[p*SX_STRIDE];
#pragma unroll
                for (int i = 0; i < 4; i++) {
                    float wv = wB[i*SW_STRIDE + p];
                    ull wp = pack2(wv, wv);
                    aC0[i] = fma2(wp, cp.x,  aC0[i]);
                    aC1[i] = fma2(wp, cp.y,  aC1[i]);
                    aS0[i] = fma2(wp, spv.x, aS0[i]);
                    aS1[i] = fma2(wp, spv.y, aS1[i]);
                }
            }
            float* rr = &sR[tid*SR_STRIDE];
#pragma unroll
            for (int i = 0; i < 4; i++) {
                *(ull*)&rr[i*4]        = aC0[i];
                *(ull*)&rr[i*4 + 2]    = aC1[i];
                *(ull*)&rr[16 + i*4]   = aS0[i];
                *(ull*)&rr[16 + i*4+2] = aS1[i];
            }
        }
        __syncthreads();

        /* ---- reduce + elementwise: all 256 threads, 4 cols each ---- */
        {
            int wr = ((row >> 2) << 3) + cf;
            int ib = (row & 3) * 4;
            float wc4[4] = {0.f, 0.f, 0.f, 0.f};
            float ws4[4] = {0.f, 0.f, 0.f, 0.f};
#pragma unroll
            for (int ksr = 0; ksr < 4; ksr++) {
                const float* r = &sR[(ksr*64 + wr)*SR_STRIDE];
                float4 c4 = *(const float4*)&r[ib];
                float4 s4 = *(const float4*)&r[16 + ib];
                wc4[0] += c4.x; wc4[1] += c4.y; wc4[2] += c4.z; wc4[3] += c4.w;
                ws4[0] += s4.x; ws4[1] += s4.y; ws4[2] += s4.z; ws4[3] += s4.w;
            }

            float4 fc = *(const float4*)&sC[so];
            float4 fs = *(const float4*)&sS[so];
            float ce[4] = {fc.x, fc.y, fc.z, fc.w};
            float se[4] = {fs.x, fs.y, fs.z, fs.w};
            float kv[4];
#pragma unroll
            for (int j = 0; j < 4; j++)
                kv[j] = fmaf(se[j], wc4[j] - cAnc, ce[j] * (sAnc - ws4[j]));

            float4 p0 = *(const float4*)&sP[so];
            float ph[4] = {p0.x, p0.y, p0.z, p0.w};
            float phiN[4];
            if (sub == 0) {
                *(float4*)&sA[so] = make_float4(kv[0], kv[1], kv[2], kv[3]);
#pragma unroll
                for (int j = 0; j < 4; j++) phiN[j] = fmaf(cNext, kv[j], ph[j]);
            } else if (sub == 3) {
                float4 a0 = *(const float4*)&sA[so];
                float av[4] = {a0.x, a0.y, a0.z, a0.w};
#pragma unroll
                for (int j = 0; j < 4; j++)
                    phiN[j] = fmaf(DT/6.0f, av[j] + kv[j], ph[j]);
                *(float4*)&sP[so] = make_float4(phiN[0], phiN[1], phiN[2], phiN[3]);
            } else {
                float4 a0 = *(const float4*)&sA[so];
                float av[4] = {a0.x, a0.y, a0.z, a0.w};
#pragma unroll
                for (int j = 0; j < 4; j++) av[j] = fmaf(2.0f, kv[j], av[j]);
                *(float4*)&sA[so] = make_float4(av[0], av[1], av[2], av[3]);
#pragma unroll
                for (int j = 0; j < 4; j++) phiN[j] = fmaf(cNext, kv[j], ph[j]);
            }

            if (e < NEV-1) {
                float cn[4], sn[4];
#pragma unroll
                for (int j = 0; j < 4; j++)
                    __sincosf(phiN[j], &sn[j], &cn[j]);
                *(float4*)&sC[so] = make_float4(cn[0], cn[1], cn[2], cn[3]);
                *(float4*)&sS[so] = make_float4(sn[0], sn[1], sn[2], sn[3]);
            }
        }

        if (e < NEV-1) {
            __syncthreads();
            m_tail(sC, sS, sXC, sXS, g_m[bufW], r0);
            /* ---- group barrier: 32 CTAs of this row group ---- */
            __syncthreads();
            if (tid == 0) {
                __threadfence();
                atomicAdd(&g_cnt[grp*NEV + e], 1u);
                volatile unsigned* c = &g_cnt[grp*NEV + e];
                while (*c < (unsigned)GXS) { }
                __threadfence();
            }
            __syncthreads();
        }
    }

    /* ---- fused readout: partial logits over this CTA's 32-col chunk ---- */
    {
        float4 p0 = *(const float4*)&sP[so];
        float ph4[4] = {p0.x, p0.y, p0.z, p0.w};
        float cc[4], ssn[4];
#pragma unroll
        for (int j = 0; j < 4; j++)
            sincosf(ph4[j], &ssn[j], &cc[j]);   /* accurate: feeds output */

        float part[COUT];
#pragma unroll
        for (int cls = 0; cls < COUT; cls++) {
            const float* wr = &Wout[cls*(2*NN) + n0 + cf*4];
            float4 wcv = *(const float4*)wr;
            float4 wsv = *(const float4*)(wr + NN);
            float a = cc[0]*wcv.x + ssn[0]*wsv.x;
            a = fmaf(cc[1], wcv.y, a); a = fmaf(ssn[1], wsv.y, a);
            a = fmaf(cc[2], wcv.z, a); a = fmaf(ssn[2], wsv.z, a);
            a = fmaf(cc[3], wcv.w, a); a = fmaf(ssn[3], wsv.w, a);
            part[cls] = a;
        }
#pragma unroll
        for (int cls = 0; cls < COUT; cls++)
#pragma unroll
            for (int w = 1; w < 8; w <<= 1)
                part[cls] += __shfl_xor_sync(0xffffffffu, part[cls], w);
        if (cf == 0)
#pragma unroll
            for (int cls = 0; cls < COUT; cls++)
                atomicAdd(&out[(r0+row)*COUT + cls], part[cls]);
    }
}

/* ================= host ================================================= */
extern "C" void kernel_launch(void* const* d_in, const int* in_sizes, int n_in,
                              void* d_out, int out_size) {
    (void)in_sizes; (void)n_in; (void)out_size;
    const float* x    = (const float*)d_in[0];
    const float* Wenc = (const float*)d_in[1];
    const float* benc = (const float*)d_in[2];
    const float* xi   = (const float*)d_in[3];
    const float* Wout = (const float*)d_in[4];
    const float* bout = (const float*)d_in[5];
    float* out = (float*)d_out;

    cudaFuncSetAttribute(k_encoder, cudaFuncAttributeMaxDynamicSharedMemorySize, SMEM_BYTES);
    cudaFuncSetAttribute(k_run,     cudaFuncAttributeMaxDynamicSharedMemorySize, SMEM_BYTES);

    EvalConsts ec;
    for (int e = 0; e < NEV; e++) {
        int step = e >> 2, sub = e & 3;
        float t0 = (float)step * DT;
        float tE = (sub == 0) ? t0 : ((sub == 3) ? t0 + DT : t0 + 0.5f*DT);
        float argf = OME * tE;
        double sa = sin((double)argf), ca = cos((double)argf);
        ec.sA[e] = (float)((double)A_ANC * sa);
        ec.cA[e] = (float)((double)A_ANC * ca);
        ec.cN[e] = (sub == 2) ? DT : 0.5f*DT;
    }

    k_init<<<512, 256>>>(xi, bout, out);

    dim3 grid(GXS, NGRP);            /* 32 x 8 = 256 CTAs, all resident */
    k_encoder<<<grid, 256, SMEM_BYTES>>>(x, Wenc, benc);
    k_run<<<grid, 256, SMEM_BYTES>>>(ec, Wout, out);
}

// round 17
// speedup vs baseline: 1.2345x; 1.0298x over previous
#include <cuda_runtime.h>
#include <math.h>

#define BATCH 256
#define NN    1024
#define PP    128
#define DIN   784
#define COUT  10
#define CH    32                     /* columns per CTA */
#define NEV   64                     /* RK4 evals */
#define NGRP  8                      /* row groups (blockIdx.y) */
#define GXS   32                     /* CTAs per group (blockIdx.x) */

#define TWO_PI_F 6.283185307179586f
#define DT       0.03125f
#define BETA_N   (2.0f/1024.0f)
#define A_ANC    0.08f
#define OME      (TWO_PI_F*200.0f)

typedef unsigned long long ull;

__device__ __forceinline__ ull pack2(float a, float b) {
    ull r; asm("mov.b64 %0,{%1,%2};" : "=l"(r) : "f"(a), "f"(b)); return r;
}
__device__ __forceinline__ ull fma2(ull a, ull b, ull c) {
    ull d; asm("fma.rn.f32x2 %0,%1,%2,%3;" : "=l"(d) : "l"(a), "l"(b), "l"(c));
    return d;
}
__device__ __forceinline__ float hadd2(ull a) {
    float lo, hi;
    asm("mov.b64 {%0,%1},%2;" : "=f"(lo), "=f"(hi) : "l"(a));
    return lo + hi;
}
__device__ __forceinline__ unsigned su32(const void* p) {
    return (unsigned)__cvta_generic_to_shared(p);
}
#define CP16(dst, src) \
    asm volatile("cp.async.cg.shared.global [%0], [%1], 16;" :: "r"(dst), "l"(src))
#define CP_COMMIT() asm volatile("cp.async.commit_group;")
#define CP_WAIT(n)  asm volatile("cp.async.wait_group %0;" :: "n"(n))

/* m slot permutation: pattern p = pb + 32j stored at slot pb*4 + j ->
   each m_tail thread's 4 partials per row are CONTIGUOUS -> one
   atomicAdd(float4). Inverse: p(s) = (s>>2) + 32*(s&3). */

struct EvalConsts { float sA[NEV]; float cA[NEV]; float cN[NEV]; };

/* ---- device scratch ---- */
__device__ float g_xc[PP*NN];
__device__ float g_xs[PP*NN];
__device__ float g_phi[BATCH*NN];
__device__ float g_fc[BATCH*NN];
__device__ float g_fs[BATCH*NN];
__device__ float g_m[3][BATCH*PP];   /* permuted slot layout */
__device__ unsigned g_cnt[NGRP*NEV];

/* ---- k_run shared layout (floats) ---- */
#define SW_STRIDE 130
#define SX_STRIDE 36
#define SC_STRIDE 36
#define SR_STRIDE 36
#define SW_FLOATS (32*SW_STRIDE)
#define SX_FLOATS (128*SX_STRIDE)
#define SC_FLOATS (32*SC_STRIDE)
#define SR_FLOATS (256*SR_STRIDE)
#define SMEM_FLOATS (SW_FLOATS + 2*SX_FLOATS + 4*SC_FLOATS + SR_FLOATS)
#define SMEM_BYTES  (SMEM_FLOATS*4)  /* 108800 -> 2 CTAs/SM */

/* ---- encoder-private layout: 4 staging buffers + xi tiles + features --- */
#define EB_STRIDE 68
#define EB_FLOATS (32*EB_STRIDE)     /* 2176 per buffer */
#define E_XC (4*EB_FLOATS)           /* 8704  */
#define E_XS (E_XC + SX_FLOATS)      /* 13312 */
#define E_C  (E_XS + SX_FLOATS)      /* 17920 */
#define E_S  (E_C + SC_FLOATS)       /* 19072; end 20224 < SMEM_FLOATS */

/* ================= init: trig tables, m bufs, counters, out=bias ======== */
__global__ void k_init(const float* __restrict__ xi,
                       const float* __restrict__ bout,
                       float* __restrict__ out) {
    int i = blockIdx.x*256 + threadIdx.x;
    if (i < PP*NN) {
        float v = xi[i];
        g_xc[i] = cosf(v);
        g_xs[i] = sinf(v);
    }
    if (i < BATCH*PP) { g_m[0][i] = 0.f; g_m[1][i] = 0.f; }
    if (i < NGRP*NEV) g_cnt[i] = 0u;
    if (i < BATCH*COUT) out[i] = bout[i % COUT];
}

__device__ __forceinline__ void load_xtiles(float* sXC, float* sXS, int n0) {
    for (int i = threadIdx.x; i < 128*8; i += 256) {
        int p = i >> 3, q = (i & 7) << 2;
        float4 a = *(const float4*)&g_xc[p*NN + n0 + q];
        *(float4*)&sXC[p*SX_STRIDE + q] = a;
        float4 b = *(const float4*)&g_xs[p*NN + n0 + q];
        *(float4*)&sXS[p*SX_STRIDE + q] = b;
    }
}

/* partial m over this CTA's 32-col chunk; fma2, 4 rows x 4 patterns;
   permuted slots -> ONE float4 atomic per row (4 total, RED.v4 path). */
__device__ __forceinline__ void m_tail(const float* sC, const float* sS,
                                       const float* sXC, const float* sXS,
                                       float* mbuf, int r0) {
    int rb = threadIdx.x >> 5;
    int pb = threadIdx.x & 31;
    ull acc[16];
#pragma unroll
    for (int i = 0; i < 16; i++) acc[i] = 0ull;
    const float* cB  = sC  + (rb*4)*SC_STRIDE;
    const float* sB  = sS  + (rb*4)*SC_STRIDE;
    const float* xcB = sXC + pb*SX_STRIDE;
    const float* xsB = sXS + pb*SX_STRIDE;
#pragma unroll
    for (int nn = 0; nn < CH; nn += 4) {
        ulonglong2 cr[4], sr[4];
#pragma unroll
        for (int r = 0; r < 4; r++) {
            cr[r] = *(const ulonglong2*)&cB[r*SC_STRIDE + nn];
            sr[r] = *(const ulonglong2*)&sB[r*SC_STRIDE + nn];
        }
#pragma unroll
        for (int j = 0; j < 4; j++) {
            ulonglong2 xc2 = *(const ulonglong2*)&xcB[j*32*SX_STRIDE + nn];
            ulonglong2 xs2 = *(const ulonglong2*)&xsB[j*32*SX_STRIDE + nn];
#pragma unroll
            for (int r = 0; r < 4; r++) {
                ull a = acc[j*4 + r];
                a = fma2(cr[r].x, xc2.x, a);
                a = fma2(cr[r].y, xc2.y, a);
                a = fma2(sr[r].x, xs2.x, a);
                a = fma2(sr[r].y, xs2.y, a);
                acc[j*4 + r] = a;
            }
        }
    }
#pragma unroll
    for (int r = 0; r < 4; r++) {
        float4 v = make_float4(hadd2(acc[0*4 + r]), hadd2(acc[1*4 + r]),
                               hadd2(acc[2*4 + r]), hadd2(acc[3*4 + r]));
        atomicAdd((float4*)&mbuf[(r0 + rb*4 + r)*PP + pb*4], v);
    }
}

/* ================= encoder: double-buffered cp.async pipeline ===========
   Chunk = 64 k (12 full + 16 tail), 1 barrier per chunk. Thread owns
   cols ng + 8i (interleave -> conflict-free sB float4 rows).           */
__global__ void __launch_bounds__(256, 2)
k_encoder(const float* __restrict__ x,
          const float* __restrict__ Wenc,
          const float* __restrict__ benc) {
    extern __shared__ float sm[];
    float* sXC = sm + E_XC;
    float* sXS = sm + E_XS;
    float* sC  = sm + E_C;
    float* sS  = sm + E_S;

    int n0 = blockIdx.x*CH, r0 = blockIdx.y*32;
    int tid = threadIdx.x;
    int row = tid >> 3, ng = tid & 7;

    /* buffers: A = x staging, B = Wenc staging, two of each */
    float* bufA[2] = { sm,               sm + EB_FLOATS };
    float* bufB[2] = { sm + 2*EB_FLOATS, sm + 3*EB_FLOATS };

    /* issue chunk ch (d0 = ch*64, ck = 64 full / 16 tail) into buf ch&1 */
    auto issue_full = [&](int ch) {
        int d0 = ch*64, b = ch & 1;
#pragma unroll
        for (int it = 0; it < 2; it++) {
            int q = tid + it*256;        /* 512 quads per array */
            int r = q >> 4, qc = (q & 15) << 2;
            CP16(su32(&bufA[b][r*EB_STRIDE + qc]), &x[(r0+r)*DIN + d0 + qc]);
            CP16(su32(&bufB[b][r*EB_STRIDE + qc]), &Wenc[(n0+r)*DIN + d0 + qc]);
        }
        CP_COMMIT();
    };
    auto issue_tail = [&]() {            /* ch = 12, ck = 16 */
        int d0 = 768, b = 0;
        if (tid < 128) {                 /* 128 quads per array */
            int r = tid >> 2, qc = (tid & 3) << 2;
            CP16(su32(&bufA[b][r*EB_STRIDE + qc]), &x[(r0+r)*DIN + d0 + qc]);
            CP16(su32(&bufB[b][r*EB_STRIDE + qc]), &Wenc[(n0+r)*DIN + d0 + qc]);
        }
        CP_COMMIT();
    };

    float acc[4];
#pragma unroll
    for (int i = 0; i < 4; i++) acc[i] = 0.f;

    issue_full(0);
    for (int ch = 0; ch < 13; ch++) {
        CP_WAIT(0);
        __syncthreads();                 /* chunk ch visible; prev compute done */
        if (ch + 1 < 12)       issue_full(ch + 1);
        else if (ch + 1 == 12) issue_tail();

        int b = ch & 1;
        const float* Ab = &bufA[b][row*EB_STRIDE];
        const float* Bb = &bufB[b][ng*EB_STRIDE];
        int ck = (ch < 12) ? 64 : 16;
#pragma unroll 4
        for (int j = 0; j < ck; j += 4) {
            float4 a4 = *(const float4*)&Ab[j];
#pragma unroll
            for (int i = 0; i < 4; i++) {
                float4 b4 = *(const float4*)&Bb[i*8*EB_STRIDE + j];
                acc[i] = fmaf(a4.x, b4.x, acc[i]);
                acc[i] = fmaf(a4.y, b4.y, acc[i]);
                acc[i] = fmaf(a4.z, b4.z, acc[i]);
                acc[i] = fmaf(a4.w, b4.w, acc[i]);
            }
        }
    }

    load_xtiles(sXC, sXS, n0);

#pragma unroll
    for (int i = 0; i < 4; i++) {
        int col = ng + 8*i;
        float z  = acc[i] + benc[n0 + col];
        float p0 = TWO_PI_F / (1.0f + expf(-z));
        int gi = (r0+row)*NN + n0 + col;
        g_phi[gi] = p0;
        float ss, cc;
        __sincosf(p0, &ss, &cc);
        g_fc[gi] = cc;
        g_fs[gi] = ss;
        sC[row*SC_STRIDE + col] = cc;
        sS[row*SC_STRIDE + col] = ss;
    }
    __syncthreads();
    m_tail(sC, sS, sXC, sXS, g_m[0], r0);
}

/* ================= persistent RK4 kernel + fused readout ================ */
__global__ void __launch_bounds__(256, 2)
k_run(EvalConsts ec, const float* __restrict__ Wout, float* __restrict__ out) {
    extern __shared__ float sm[];
    float* sW  = sm;
    float* sXC = sm + SW_FLOATS;
    float* sXS = sXC + SX_FLOATS;
    float* sC  = sXS + SX_FLOATS;
    float* sS  = sC + SC_FLOATS;
    float* sP  = sS + SC_FLOATS;
    float* sA  = sP + SC_FLOATS;
    float* sR  = sA + SC_FLOATS;

    int n0 = blockIdx.x*CH, r0 = blockIdx.y*32;
    int tid = threadIdx.x;
    int row = tid >> 3, cf = tid & 7;
    int so  = row*SC_STRIDE + cf*4;
    int gso = (r0+row)*NN + n0 + cf*4;
    int cta = blockIdx.y*GXS + blockIdx.x;
    int grp = blockIdx.y;

    /* ---- one-time loads: xi tiles + state ---- */
#pragma unroll
    for (int it = 0; it < 4; it++) {
        int i = tid + it*256;
        int p = i >> 3, q = (i & 7) << 2;
        CP16(su32(&sXC[p*SX_STRIDE + q]), &g_xc[p*NN + n0 + q]);
        CP16(su32(&sXS[p*SX_STRIDE + q]), &g_xs[p*NN + n0 + q]);
    }
    CP16(su32(&sC[so]), &g_fc[gso]);
    CP16(su32(&sS[so]), &g_fs[gso]);
    CP16(su32(&sP[so]), &g_phi[gso]);
    CP_COMMIT();
    CP_WAIT(0);
    __syncthreads();

    for (int e = 0; e < NEV; e++) {
        int sub  = e & 3;
        int bufR = e % 3, bufW = (e + 1) % 3, bufZ = (e + 2) % 3;
        float sAnc = ec.sA[e], cAnc = ec.cA[e], cNext = ec.cN[e];

        /* m slot slice: direct LDG into registers (issued early) */
        float mv[16];
        {
            const float* gmp = &g_m[bufR][(r0+row)*PP + cf*16];
            float4 a0 = *(const float4*)&gmp[0];
            float4 a1 = *(const float4*)&gmp[4];
            float4 a2 = *(const float4*)&gmp[8];
            float4 a3 = *(const float4*)&gmp[12];
            mv[0]=a0.x;  mv[1]=a0.y;  mv[2]=a0.z;  mv[3]=a0.w;
            mv[4]=a1.x;  mv[5]=a1.y;  mv[6]=a1.z;  mv[7]=a1.w;
            mv[8]=a2.x;  mv[9]=a2.y;  mv[10]=a2.z; mv[11]=a2.w;
            mv[12]=a3.x; mv[13]=a3.y; mv[14]=a3.z; mv[15]=a3.w;
        }

        /* zero the buffer used two evals ahead (own group rows only) */
        if (tid < 128) g_m[bufZ][cta*128 + tid] = 0.f;

        /* ---- softmax (arg in [-2,2]); un-permute slots on sW write ---- */
        {
            float a[16];
            float ssum = 0.f;
#pragma unroll
            for (int j = 0; j < 16; j++) {
                a[j] = __expf(mv[j] * BETA_N);
                ssum += a[j];
            }
#pragma unroll
            for (int w = 1; w < 8; w <<= 1)
                ssum += __shfl_xor_sync(0xffffffffu, ssum, w);
            float inv = 1.0f / ssum;
#pragma unroll
            for (int j = 0; j < 16; j++) {
                int s = cf*16 + j;
                int p = (s >> 2) + 32*(s & 3);
                sW[row*SW_STRIDE + p] = a[j] * inv;
            }
        }
        __syncthreads();

        /* ---- coupling GEMM, tile 4 rows x 4 cols (f32x2), K-split 4 ---- */
        {
            int ks   = tid >> 6;
            int r6   = tid & 63;
            int rowg = r6 >> 3;
            int colg = r6 & 7;
            ull aC0[4], aC1[4], aS0[4], aS1[4];
#pragma unroll
            for (int i = 0; i < 4; i++) { aC0[i]=0ull; aC1[i]=0ull; aS0[i]=0ull; aS1[i]=0ull; }
            const float* wB  = &sW[(rowg*4)*SW_STRIDE + ks*32];
            const float* xcB = &sXC[(ks*32)*SX_STRIDE + colg*4];
            const float* xsB = &sXS[(ks*32)*SX_STRIDE + colg*4];
#pragma unroll 4
            for (int p = 0; p < 32; p++) {
                ulonglong2 cp = *(const ulonglong2*)&xcB[p*SX_STRIDE];
                ulonglong2 spv = *(const ulonglong2*)&xsB[p*SX_STRIDE];
#pragma unroll
                for (int i = 0; i < 4; i++) {
                    float wv = wB[i*SW_STRIDE + p];
                    ull wp = pack2(wv, wv);
                    aC0[i] = fma2(wp, cp.x,  aC0[i]);
                    aC1[i] = fma2(wp, cp.y,  aC1[i]);
                    aS0[i] = fma2(wp, spv.x, aS0[i]);
                    aS1[i] = fma2(wp, spv.y, aS1[i]);
                }
            }
            float* rr = &sR[tid*SR_STRIDE];
#pragma unroll
            for (int i = 0; i < 4; i++) {
                *(ull*)&rr[i*4]        = aC0[i];
                *(ull*)&rr[i*4 + 2]    = aC1[i];
                *(ull*)&rr[16 + i*4]   = aS0[i];
                *(ull*)&rr[16 + i*4+2] = aS1[i];
            }
        }
        __syncthreads();

        /* ---- reduce + elementwise: all 256 threads, 4 cols each ---- */
        {
            int wr = ((row >> 2) << 3) + cf;
            int ib = (row & 3) * 4;
            float wc4[4] = {0.f, 0.f, 0.f, 0.f};
            float ws4[4] = {0.f, 0.f, 0.f, 0.f};
#pragma unroll
            for (int ksr = 0; ksr < 4; ksr++) {
                const float* r = &sR[(ksr*64 + wr)*SR_STRIDE];
                float4 c4 = *(const float4*)&r[ib];
                float4 s4 = *(const float4*)&r[16 + ib];
                wc4[0] += c4.x; wc4[1] += c4.y; wc4[2] += c4.z; wc4[3] += c4.w;
                ws4[0] += s4.x; ws4[1] += s4.y; ws4[2] += s4.z; ws4[3] += s4.w;
            }

            float4 fc = *(const float4*)&sC[so];
            float4 fs = *(const float4*)&sS[so];
            float ce[4] = {fc.x, fc.y, fc.z, fc.w};
            float se[4] = {fs.x, fs.y, fs.z, fs.w};
            float kv[4];
#pragma unroll
            for (int j = 0; j < 4; j++)
                kv[j] = fmaf(se[j], wc4[j] - cAnc, ce[j] * (sAnc - ws4[j]));

            float4 p0 = *(const float4*)&sP[so];
            float ph[4] = {p0.x, p0.y, p0.z, p0.w};
            float phiN[4];
            if (sub == 0) {
                *(float4*)&sA[so] = make_float4(kv[0], kv[1], kv[2], kv[3]);
#pragma unroll
                for (int j = 0; j < 4; j++) phiN[j] = fmaf(cNext, kv[j], ph[j]);
            } else if (sub == 3) {
                float4 a0 = *(const float4*)&sA[so];
                float av[4] = {a0.x, a0.y, a0.z, a0.w};
#pragma unroll
                for (int j = 0; j < 4; j++)
                    phiN[j] = fmaf(DT/6.0f, av[j] + kv[j], ph[j]);
                *(float4*)&sP[so] = make_float4(phiN[0], phiN[1], phiN[2], phiN[3]);
            } else {
                float4 a0 = *(const float4*)&sA[so];
                float av[4] = {a0.x, a0.y, a0.z, a0.w};
#pragma unroll
                for (int j = 0; j < 4; j++) av[j] = fmaf(2.0f, kv[j], av[j]);
                *(float4*)&sA[so] = make_float4(av[0], av[1], av[2], av[3]);
#pragma unroll
                for (int j = 0; j < 4; j++) phiN[j] = fmaf(cNext, kv[j], ph[j]);
            }

            if (e < NEV-1) {
                float cn[4], sn[4];
#pragma unroll
                for (int j = 0; j < 4; j++)
                    __sincosf(phiN[j], &sn[j], &cn[j]);
                *(float4*)&sC[so] = make_float4(cn[0], cn[1], cn[2], cn[3]);
                *(float4*)&sS[so] = make_float4(sn[0], sn[1], sn[2], sn[3]);
            }
        }

        if (e < NEV-1) {
            __syncthreads();
            m_tail(sC, sS, sXC, sXS, g_m[bufW], r0);
            /* ---- group barrier: 32 CTAs of this row group ---- */
            __syncthreads();
            if (tid == 0) {
                __threadfence();
                atomicAdd(&g_cnt[grp*NEV + e], 1u);
                volatile unsigned* c = &g_cnt[grp*NEV + e];
                while (*c < (unsigned)GXS) { }
                __threadfence();
            }
            __syncthreads();
        }
    }

    /* ---- fused readout: partial logits over this CTA's 32-col chunk ---- */
    {
        float4 p0 = *(const float4*)&sP[so];
        float ph4[4] = {p0.x, p0.y, p0.z, p0.w};
        float cc[4], ssn[4];
#pragma unroll
        for (int j = 0; j < 4; j++)
            sincosf(ph4[j], &ssn[j], &cc[j]);   /* accurate: feeds output */

        float part[COUT];
#pragma unroll
        for (int cls = 0; cls < COUT; cls++) {
            const float* wr = &Wout[cls*(2*NN) + n0 + cf*4];
            float4 wcv = *(const float4*)wr;
            float4 wsv = *(const float4*)(wr + NN);
            float a = cc[0]*wcv.x + ssn[0]*wsv.x;
            a = fmaf(cc[1], wcv.y, a); a = fmaf(ssn[1], wsv.y, a);
            a = fmaf(cc[2], wcv.z, a); a = fmaf(ssn[2], wsv.z, a);
            a = fmaf(cc[3], wcv.w, a); a = fmaf(ssn[3], wsv.w, a);
            part[cls] = a;
        }
#pragma unroll
        for (int cls = 0; cls < COUT; cls++)
#pragma unroll
            for (int w = 1; w < 8; w <<= 1)
                part[cls] += __shfl_xor_sync(0xffffffffu, part[cls], w);
        if (cf == 0)
#pragma unroll
            for (int cls = 0; cls < COUT; cls++)
                atomicAdd(&out[(r0+row)*COUT + cls], part[cls]);
    }
}

/* ================= host ================================================= */
extern "C" void kernel_launch(void* const* d_in, const int* in_sizes, int n_in,
                              void* d_out, int out_size) {
    (void)in_sizes; (void)n_in; (void)out_size;
    const float* x    = (const float*)d_in[0];
    const float* Wenc = (const float*)d_in[1];
    const float* benc = (const float*)d_in[2];
    const float* xi   = (const float*)d_in[3];
    const float* Wout = (const float*)d_in[4];
    const float* bout = (const float*)d_in[5];
    float* out = (float*)d_out;

    cudaFuncSetAttribute(k_encoder, cudaFuncAttributeMaxDynamicSharedMemorySize, SMEM_BYTES);
    cudaFuncSetAttribute(k_run,     cudaFuncAttributeMaxDynamicSharedMemorySize, SMEM_BYTES);

    EvalConsts ec;
    for (int e = 0; e < NEV; e++) {
        int step = e >> 2, sub = e & 3;
        float t0 = (float)step * DT;
        float tE = (sub == 0) ? t0 : ((sub == 3) ? t0 + DT : t0 + 0.5f*DT);
        float argf = OME * tE;
        double sa = sin((double)argf), ca = cos((double)argf);
        ec.sA[e] = (float)((double)A_ANC * sa);
        ec.cA[e] = (float)((double)A_ANC * ca);
        ec.cN[e] = (sub == 2) ? DT : 0.5f*DT;
    }

    k_init<<<512, 256>>>(xi, bout, out);

    dim3 grid(GXS, NGRP);            /* 32 x 8 = 256 CTAs, all resident */
    k_encoder<<<grid, 256, SMEM_BYTES>>>(x, Wenc, benc);
    k_run<<<grid, 256, SMEM_BYTES>>>(ec, Wout, out);
}